// round 1
// baseline (speedup 1.0000x reference)
#include <cuda_runtime.h>
#include <math.h>

#define SEQ   2048
#define HID   2048
#define NHEADS 16
#define NKVH   4
#define HDIM   128
#define NEXP   8
#define IDIM   1024
#define ATT_SCALE 0.08838834764831845f   // 128^-0.5

// ---------------- scratch (device globals; no dynamic allocation) ----------------
__device__ float g_x1[SEQ * HID];                 // ln1 output
__device__ float g_q[SEQ * NHEADS * HDIM];        // Q
__device__ float g_k[SEQ * NKVH * HDIM];          // K
__device__ float g_v[SEQ * NKVH * HDIM];          // V
__device__ float g_attn[SEQ * NHEADS * HDIM];     // attention out (pre-wo)
__device__ float g_x3[SEQ * HID];                 // ln2 output
__device__ float g_moeh[2 * SEQ * IDIM];          // MoE hidden, slot-major (4096 x 1024)
__device__ int   g_topidx[SEQ * 2];
__device__ float g_topw[SEQ * 2];
__device__ int   g_cnt[NEXP];
__device__ int   g_off[NEXP];
__device__ int   g_tok[NEXP * SEQ];
__device__ float g_tw[NEXP * SEQ];

// ---------------- RMSNorm: one block per row ----------------
__global__ void rmsnorm_kernel(const float* __restrict__ x, const float* __restrict__ w,
                               float* __restrict__ y, int cols) {
  int row = blockIdx.x;
  const float* xr = x + (size_t)row * cols;
  float ss = 0.f;
  for (int i = threadIdx.x; i < cols; i += blockDim.x) { float v = xr[i]; ss += v * v; }
#pragma unroll
  for (int o = 16; o; o >>= 1) ss += __shfl_xor_sync(0xffffffffu, ss, o);
  __shared__ float sred[8];
  __shared__ float sscale;
  if ((threadIdx.x & 31) == 0) sred[threadIdx.x >> 5] = ss;
  __syncthreads();
  if (threadIdx.x == 0) {
    float t = 0.f;
#pragma unroll
    for (int i = 0; i < 8; i++) t += sred[i];
    sscale = rsqrtf(t / (float)cols + 1e-6f);
  }
  __syncthreads();
  float sc = sscale;
  float* yr = y + (size_t)row * cols;
  for (int i = threadIdx.x; i < cols; i += blockDim.x) yr[i] = xr[i] * sc * w[i];
}

// ---------------- generic fp32 GEMM: C = A[M,K] @ B[K,N] (+D) ----------------
// BM=BN=64, BK=16, 256 threads, 4x4 micro-tile.
template <bool ADD>
__global__ void gemm_kernel(const float* __restrict__ A, const float* __restrict__ B,
                            const float* __restrict__ D, float* __restrict__ C,
                            int N, int K) {
  __shared__ float As[16][64];   // As[k][m]
  __shared__ float Bs[16][64];   // Bs[k][n]
  int tid = threadIdx.x;
  int tx = tid & 15, ty = tid >> 4;
  int m0 = blockIdx.x * 64, n0 = blockIdx.y * 64;
  int am = tid >> 2, ak = (tid & 3) << 2;
  int bk = tid >> 4, bn = (tid & 15) << 2;
  const float* Ap = A + (size_t)(m0 + am) * K + ak;
  const float* Bp = B + (size_t)bk * N + n0 + bn;
  float acc[4][4] = {};
  for (int k0 = 0; k0 < K; k0 += 16) {
    float4 av = *(const float4*)(Ap + k0);
    As[ak + 0][am] = av.x; As[ak + 1][am] = av.y;
    As[ak + 2][am] = av.z; As[ak + 3][am] = av.w;
    *(float4*)&Bs[bk][bn] = *(const float4*)(Bp + (size_t)k0 * N);
    __syncthreads();
#pragma unroll
    for (int kk = 0; kk < 16; kk++) {
      float4 a4 = *(const float4*)&As[kk][ty << 2];
      float4 b4 = *(const float4*)&Bs[kk][tx << 2];
      float ar[4] = {a4.x, a4.y, a4.z, a4.w};
      float br[4] = {b4.x, b4.y, b4.z, b4.w};
#pragma unroll
      for (int i = 0; i < 4; i++)
#pragma unroll
        for (int j = 0; j < 4; j++) acc[i][j] += ar[i] * br[j];
    }
    __syncthreads();
  }
#pragma unroll
  for (int i = 0; i < 4; i++) {
    int m = m0 + (ty << 2) + i;
#pragma unroll
    for (int j = 0; j < 4; j++) {
      int n = n0 + (tx << 2) + j;
      float v = acc[i][j];
      if (ADD) v += D[(size_t)m * N + n];
      C[(size_t)m * N + n] = v;
    }
  }
}

// ---------------- partial RoPE (first RD=64 dims of each head), in place ----------------
__global__ void rope_kernel(float* __restrict__ x, const float* __restrict__ cp,
                            const float* __restrict__ sp, int nheads) {
  int idx = blockIdx.x * blockDim.x + threadIdx.x;
  int total = SEQ * nheads * 32;
  if (idx >= total) return;
  int d = idx & 31;
  int h = (idx >> 5) % nheads;
  int s = idx / (nheads * 32);
  size_t base = (size_t)s * nheads * HDIM + (size_t)h * HDIM + d;
  float a = x[base], b = x[base + 32];
  float c = cp[s * 64 + d], sn = sp[s * 64 + d];
  x[base]      = a * c - b * sn;
  x[base + 32] = b * c + a * sn;
}

// ---------------- causal flash attention, fp32, Br=Bc=64 ----------------
__global__ void flash_kernel(const float* __restrict__ Q, const float* __restrict__ Kp,
                             const float* __restrict__ Vp, float* __restrict__ O) {
  extern __shared__ float sm[];
  float* Qs = sm;                 // 64 x 132 (padded)
  float* Ks = Qs + 64 * 132;      // 64 x 132
  float* Vs = Ks + 64 * 132;      // 64 x 128
  float* Ps = Vs + 64 * 128;      // 64 x 64
  int qt = blockIdx.x, head = blockIdx.y;
  int kh = head >> 2;             // GQA: 4 query heads per KV head
  int tid = threadIdx.x, tx = tid & 15, ty = tid >> 4;
  int q0 = qt * 64;

  for (int i = tid; i < 64 * 32; i += 256) {
    int r = i >> 5, d4 = (i & 31) << 2;
    *(float4*)&Qs[r * 132 + d4] =
        *(const float4*)&Q[(size_t)(q0 + r) * (NHEADS * HDIM) + head * HDIM + d4];
  }

  float m[4], l[4], co[4][8];
#pragma unroll
  for (int i = 0; i < 4; i++) {
    m[i] = -3.0e38f; l[i] = 0.f;
#pragma unroll
    for (int c = 0; c < 8; c++) co[i][c] = 0.f;
  }

  for (int kt = 0; kt <= qt; kt++) {
    __syncthreads();
    int k0 = kt * 64;
    for (int i = tid; i < 64 * 32; i += 256) {
      int r = i >> 5, d4 = (i & 31) << 2;
      size_t gb = (size_t)(k0 + r) * (NKVH * HDIM) + kh * HDIM + d4;
      *(float4*)&Ks[r * 132 + d4] = *(const float4*)&Kp[gb];
      *(float4*)&Vs[r * 128 + d4] = *(const float4*)&Vp[gb];
    }
    __syncthreads();

    float sc[4][4] = {};
    for (int d = 0; d < 128; d += 4) {
      float4 aa[4], bb[4];
#pragma unroll
      for (int i = 0; i < 4; i++) aa[i] = *(const float4*)&Qs[((ty << 2) + i) * 132 + d];
#pragma unroll
      for (int j = 0; j < 4; j++) bb[j] = *(const float4*)&Ks[((tx << 2) + j) * 132 + d];
#pragma unroll
      for (int i = 0; i < 4; i++)
#pragma unroll
        for (int j = 0; j < 4; j++)
          sc[i][j] += aa[i].x * bb[j].x + aa[i].y * bb[j].y +
                      aa[i].z * bb[j].z + aa[i].w * bb[j].w;
    }

    bool diag = (kt == qt);
#pragma unroll
    for (int i = 0; i < 4; i++) {
      int r = (ty << 2) + i;
#pragma unroll
      for (int j = 0; j < 4; j++) {
        float v = sc[i][j] * ATT_SCALE;
        if (diag && ((tx << 2) + j) > r) v = -1e30f;
        sc[i][j] = v;
      }
      float mx = fmaxf(fmaxf(sc[i][0], sc[i][1]), fmaxf(sc[i][2], sc[i][3]));
#pragma unroll
      for (int o = 8; o; o >>= 1) mx = fmaxf(mx, __shfl_xor_sync(0xffffffffu, mx, o));
      float mn = fmaxf(m[i], mx);
      float corr = __expf(m[i] - mn);
      m[i] = mn;
      float rs = 0.f;
#pragma unroll
      for (int j = 0; j < 4; j++) {
        float p = __expf(sc[i][j] - mn);
        sc[i][j] = p; rs += p;
      }
#pragma unroll
      for (int o = 8; o; o >>= 1) rs += __shfl_xor_sync(0xffffffffu, rs, o);
      l[i] = l[i] * corr + rs;
#pragma unroll
      for (int c = 0; c < 8; c++) co[i][c] *= corr;
#pragma unroll
      for (int j = 0; j < 4; j++) Ps[r * 64 + (tx << 2) + j] = sc[i][j];
    }
    __syncthreads();

    for (int j = 0; j < 64; j++) {
      float4 v0 = *(const float4*)&Vs[j * 128 + (tx << 3)];
      float4 v1 = *(const float4*)&Vs[j * 128 + (tx << 3) + 4];
#pragma unroll
      for (int i = 0; i < 4; i++) {
        float p = Ps[((ty << 2) + i) * 64 + j];
        co[i][0] += p * v0.x; co[i][1] += p * v0.y;
        co[i][2] += p * v0.z; co[i][3] += p * v0.w;
        co[i][4] += p * v1.x; co[i][5] += p * v1.y;
        co[i][6] += p * v1.z; co[i][7] += p * v1.w;
      }
    }
  }

#pragma unroll
  for (int i = 0; i < 4; i++) {
    float inv = 1.f / l[i];
    int r = q0 + (ty << 2) + i;
#pragma unroll
    for (int c = 0; c < 8; c++)
      O[(size_t)r * (NHEADS * HDIM) + head * HDIM + (tx << 3) + c] = co[i][c] * inv;
  }
}

// ---------------- MoE gating: sigmoid, top-2, normalized weights ----------------
__global__ void gate_kernel(const float* __restrict__ X, const float* __restrict__ GW,
                            const float* __restrict__ BE) {
  int t = blockIdx.x;
  const float* xr = X + (size_t)t * HID;
  float acc[NEXP];
#pragma unroll
  for (int e = 0; e < NEXP; e++) acc[e] = 0.f;
  for (int h = threadIdx.x; h < HID; h += blockDim.x) {
    float xv = xr[h];
    const float* g = GW + (size_t)h * NEXP;
#pragma unroll
    for (int e = 0; e < NEXP; e++) acc[e] += xv * g[e];
  }
#pragma unroll
  for (int e = 0; e < NEXP; e++)
#pragma unroll
    for (int o = 16; o; o >>= 1) acc[e] += __shfl_xor_sync(0xffffffffu, acc[e], o);
  __shared__ float ws[8][NEXP];
  if ((threadIdx.x & 31) == 0)
#pragma unroll
    for (int e = 0; e < NEXP; e++) ws[threadIdx.x >> 5][e] = acc[e];
  __syncthreads();
  if (threadIdx.x == 0) {
    float scv[NEXP], bi[NEXP];
#pragma unroll
    for (int e = 0; e < NEXP; e++) {
      float lg = 0.f;
#pragma unroll
      for (int wdx = 0; wdx < 8; wdx++) lg += ws[wdx][e];
      scv[e] = 1.f / (1.f + expf(-lg));
      bi[e] = scv[e] + BE[e];
    }
    int i0 = 0;
    for (int e = 1; e < NEXP; e++) if (bi[e] > bi[i0]) i0 = e;
    int i1 = -1;
    for (int e = 0; e < NEXP; e++) {
      if (e == i0) continue;
      if (i1 < 0 || bi[e] > bi[i1]) i1 = e;
    }
    float w0 = scv[i0], w1 = scv[i1];
    float ssum = fmaxf(w0 + w1, 1e-12f);
    g_topidx[t * 2] = i0; g_topidx[t * 2 + 1] = i1;
    g_topw[t * 2] = w0 / ssum; g_topw[t * 2 + 1] = w1 / ssum;
  }
}

__global__ void zero_cnt_kernel() {
  if (threadIdx.x < NEXP) g_cnt[threadIdx.x] = 0;
}

__global__ void route_kernel() {
  int s = blockIdx.x * blockDim.x + threadIdx.x;
  if (s >= SEQ * 2) return;
  int e = g_topidx[s];
  float w = g_topw[s];
  int p = atomicAdd(&g_cnt[e], 1);
  g_tok[e * SEQ + p] = s >> 1;
  g_tw[e * SEQ + p] = w;
}

__global__ void offsets_kernel() {
  if (threadIdx.x == 0) {
    int s = 0;
    for (int e = 0; e < NEXP; e++) { g_off[e] = s; s += g_cnt[e]; }
  }
}

// ---------------- MoE GEMM1: h = silu(X@W1_e) * (X@W3_e), gathered rows ----------------
__global__ void moe_gemm1_kernel(const float* __restrict__ X, const float* __restrict__ W1,
                                 const float* __restrict__ W3) {
  int e = blockIdx.z;
  int ne = g_cnt[e];
  int m0 = blockIdx.x * 64;
  if (m0 >= ne) return;
  __shared__ float As[16][64];
  __shared__ float B1s[16][64];
  __shared__ float B3s[16][64];
  __shared__ int toks[64];
  int tid = threadIdx.x;
  if (tid < 64) {
    int mm = m0 + tid;
    toks[tid] = g_tok[e * SEQ + (mm < ne ? mm : ne - 1)];
  }
  __syncthreads();
  int tx = tid & 15, ty = tid >> 4;
  int n0 = blockIdx.y * 64;
  int am = tid >> 2, ak = (tid & 3) << 2;
  int bk = tid >> 4, bn = (tid & 15) << 2;
  const float* W1p = W1 + (size_t)e * HID * IDIM;
  const float* W3p = W3 + (size_t)e * HID * IDIM;
  const float* Ap = X + (size_t)toks[am] * HID + ak;
  float a1[4][4] = {}, a2[4][4] = {};
  for (int k0 = 0; k0 < HID; k0 += 16) {
    float4 av = *(const float4*)(Ap + k0);
    As[ak + 0][am] = av.x; As[ak + 1][am] = av.y;
    As[ak + 2][am] = av.z; As[ak + 3][am] = av.w;
    size_t boff = (size_t)(k0 + bk) * IDIM + n0 + bn;
    *(float4*)&B1s[bk][bn] = *(const float4*)&W1p[boff];
    *(float4*)&B3s[bk][bn] = *(const float4*)&W3p[boff];
    __syncthreads();
#pragma unroll
    for (int kk = 0; kk < 16; kk++) {
      float4 a4 = *(const float4*)&As[kk][ty << 2];
      float4 b14 = *(const float4*)&B1s[kk][tx << 2];
      float4 b34 = *(const float4*)&B3s[kk][tx << 2];
      float ar[4] = {a4.x, a4.y, a4.z, a4.w};
      float b1r[4] = {b14.x, b14.y, b14.z, b14.w};
      float b3r[4] = {b34.x, b34.y, b34.z, b34.w};
#pragma unroll
      for (int i = 0; i < 4; i++)
#pragma unroll
        for (int j = 0; j < 4; j++) {
          a1[i][j] += ar[i] * b1r[j];
          a2[i][j] += ar[i] * b3r[j];
        }
    }
    __syncthreads();
  }
#pragma unroll
  for (int i = 0; i < 4; i++) {
    int mm = m0 + (ty << 2) + i;
    if (mm < ne) {
      size_t slot = (size_t)(g_off[e] + mm) * IDIM + n0 + (tx << 2);
#pragma unroll
      for (int j = 0; j < 4; j++) {
        float g = a1[i][j], u = a2[i][j];
        g_moeh[slot + j] = g * u / (1.f + __expf(-g));  // silu(g)*u
      }
    }
  }
}

// ---------------- MoE GEMM2: out += w * (h @ W2_e), scatter-add ----------------
__global__ void moe_gemm2_kernel(const float* __restrict__ W2, float* __restrict__ Out) {
  int e = blockIdx.z;
  int ne = g_cnt[e];
  int m0 = blockIdx.x * 64;
  if (m0 >= ne) return;
  int n0 = blockIdx.y * 64;
  __shared__ float As[16][64];
  __shared__ float Bs[16][64];
  int tid = threadIdx.x;
  int tx = tid & 15, ty = tid >> 4;
  int am = tid >> 2, ak = (tid & 3) << 2;
  int bk = tid >> 4, bn = (tid & 15) << 2;
  int mrow = m0 + am; if (mrow >= ne) mrow = ne - 1;
  const float* Ap = g_moeh + (size_t)(g_off[e] + mrow) * IDIM + ak;
  const float* W2p = W2 + (size_t)e * IDIM * HID;
  float acc[4][4] = {};
  for (int k0 = 0; k0 < IDIM; k0 += 16) {
    float4 av = *(const float4*)(Ap + k0);
    As[ak + 0][am] = av.x; As[ak + 1][am] = av.y;
    As[ak + 2][am] = av.z; As[ak + 3][am] = av.w;
    *(float4*)&Bs[bk][bn] = *(const float4*)&W2p[(size_t)(k0 + bk) * HID + n0 + bn];
    __syncthreads();
#pragma unroll
    for (int kk = 0; kk < 16; kk++) {
      float4 a4 = *(const float4*)&As[kk][ty << 2];
      float4 b4 = *(const float4*)&Bs[kk][tx << 2];
      float ar[4] = {a4.x, a4.y, a4.z, a4.w};
      float br[4] = {b4.x, b4.y, b4.z, b4.w};
#pragma unroll
      for (int i = 0; i < 4; i++)
#pragma unroll
        for (int j = 0; j < 4; j++) acc[i][j] += ar[i] * br[j];
    }
    __syncthreads();
  }
#pragma unroll
  for (int i = 0; i < 4; i++) {
    int mm = m0 + (ty << 2) + i;
    if (mm < ne) {
      int t = g_tok[e * SEQ + mm];
      float w = g_tw[e * SEQ + mm];
      size_t ob = (size_t)t * HID + n0 + (tx << 2);
#pragma unroll
      for (int j = 0; j < 4; j++) atomicAdd(&Out[ob + j], w * acc[i][j]);
    }
  }
}

// ---------------- launch ----------------
extern "C" void kernel_launch(void* const* d_in, const int* in_sizes, int n_in,
                              void* d_out, int out_size) {
  const float* hidden = (const float*)d_in[0];
  // d_in[1] = attention_mask: exact causal triu(-1e9) — implemented as causal attention
  const float* cosp = (const float*)d_in[2];
  const float* sinp = (const float*)d_in[3];
  const float* ln1  = (const float*)d_in[4];
  const float* ln2  = (const float*)d_in[5];
  const float* wq   = (const float*)d_in[6];
  const float* wk   = (const float*)d_in[7];
  const float* wv   = (const float*)d_in[8];
  const float* wo   = (const float*)d_in[9];
  const float* qn   = (const float*)d_in[10];
  const float* kn   = (const float*)d_in[11];
  const float* gw   = (const float*)d_in[12];
  const float* be   = (const float*)d_in[13];
  const float* w1   = (const float*)d_in[14];
  const float* w3   = (const float*)d_in[15];
  const float* w2   = (const float*)d_in[16];
  float* out = (float*)d_out;

  float *x1, *q, *k, *v, *attn, *x3;
  cudaGetSymbolAddress((void**)&x1, g_x1);
  cudaGetSymbolAddress((void**)&q, g_q);
  cudaGetSymbolAddress((void**)&k, g_k);
  cudaGetSymbolAddress((void**)&v, g_v);
  cudaGetSymbolAddress((void**)&attn, g_attn);
  cudaGetSymbolAddress((void**)&x3, g_x3);

  // 1) ln1
  rmsnorm_kernel<<<SEQ, 256>>>(hidden, ln1, x1, HID);
  // 2) QKV projections
  gemm_kernel<false><<<dim3(32, 32), 256>>>(x1, wq, nullptr, q, 2048, 2048);
  gemm_kernel<false><<<dim3(32, 8), 256>>>(x1, wk, nullptr, k, 512, 2048);
  gemm_kernel<false><<<dim3(32, 8), 256>>>(x1, wv, nullptr, v, 512, 2048);
  // 3) q/k norm (full-width, in place) + partial RoPE
  rmsnorm_kernel<<<SEQ, 256>>>(q, qn, q, 2048);
  rmsnorm_kernel<<<SEQ, 256>>>(k, kn, k, 512);
  rope_kernel<<<(SEQ * NHEADS * 32) / 256, 256>>>(q, cosp, sinp, NHEADS);
  rope_kernel<<<(SEQ * NKVH * 32) / 256, 256>>>(k, cosp, sinp, NKVH);
  // 4) causal flash attention
  int fasmem = (64 * 132 * 2 + 64 * 128 + 64 * 64) * (int)sizeof(float);  // 116736 B
  cudaFuncSetAttribute(flash_kernel, cudaFuncAttributeMaxDynamicSharedMemorySize, fasmem);
  flash_kernel<<<dim3(32, NHEADS), 256, fasmem>>>(q, k, v, attn);
  // 5) wo + residual -> d_out (acts as res2)
  gemm_kernel<true><<<dim3(32, 32), 256>>>(attn, wo, hidden, out, 2048, 2048);
  // 6) ln2
  rmsnorm_kernel<<<SEQ, 256>>>(out, ln2, x3, HID);
  // 7) gating + routing
  gate_kernel<<<SEQ, 256>>>(x3, gw, be);
  zero_cnt_kernel<<<1, 32>>>();
  route_kernel<<<16, 256>>>();
  offsets_kernel<<<1, 32>>>();
  // 8) sparse MoE
  moe_gemm1_kernel<<<dim3(32, 16, 8), 256>>>(x3, w1, w3);
  moe_gemm2_kernel<<<dim3(32, 32, 8), 256>>>(w2, out);
}

// round 2
// speedup vs baseline: 1.9171x; 1.9171x over previous
#include <cuda_runtime.h>
#include <math.h>
#include <stdint.h>

#define SEQ   2048
#define HID   2048
#define NHEADS 16
#define NKVH   4
#define HDIM   128
#define NEXP   8
#define IDIM   1024
#define ATT_SCALE 0.08838834764831845f   // 128^-0.5

// ---------------- scratch (device globals; no dynamic allocation) ----------------
__device__ float g_x1[SEQ * HID];                 // ln1 output
__device__ float g_q[SEQ * NHEADS * HDIM];        // Q
__device__ float g_k[SEQ * NKVH * HDIM];          // K
__device__ float g_v[SEQ * NKVH * HDIM];          // V
__device__ float g_attn[SEQ * NHEADS * HDIM];     // attention out (pre-wo)
__device__ float g_x3[SEQ * HID];                 // ln2 output
__device__ float g_moeh[2 * SEQ * IDIM];          // MoE hidden h = silu(g)*u
__device__ float g_tmp[2 * SEQ * IDIM];           // MoE raw g = X@W1
__device__ int   g_topidx[SEQ * 2];
__device__ float g_topw[SEQ * 2];
__device__ int   g_cnt[NEXP];
__device__ int   g_off[NEXP];
__device__ int   g_tok[NEXP * SEQ];
__device__ float g_tw[NEXP * SEQ];

// ---------------- helpers ----------------
__device__ __forceinline__ uint32_t f2tf(float x) {
  uint32_t r;
  asm("cvt.rna.tf32.f32 %0, %1;" : "=r"(r) : "f"(x));
  return r;
}

__device__ __forceinline__ void mma_tf32(float* c, const uint32_t* a, const uint32_t* b) {
  asm volatile(
      "mma.sync.aligned.m16n8k8.row.col.f32.tf32.tf32.f32 "
      "{%0,%1,%2,%3}, {%4,%5,%6,%7}, {%8,%9}, {%0,%1,%2,%3};"
      : "+f"(c[0]), "+f"(c[1]), "+f"(c[2]), "+f"(c[3])
      : "r"(a[0]), "r"(a[1]), "r"(a[2]), "r"(a[3]), "r"(b[0]), "r"(b[1]));
}

// ---------------- RMSNorm: one block per row ----------------
__global__ void rmsnorm_kernel(const float* __restrict__ x, const float* __restrict__ w,
                               float* __restrict__ y, int cols) {
  int row = blockIdx.x;
  const float* xr = x + (size_t)row * cols;
  float ss = 0.f;
  for (int i = threadIdx.x; i < cols; i += blockDim.x) { float v = xr[i]; ss += v * v; }
#pragma unroll
  for (int o = 16; o; o >>= 1) ss += __shfl_xor_sync(0xffffffffu, ss, o);
  __shared__ float sred[8];
  __shared__ float sscale;
  if ((threadIdx.x & 31) == 0) sred[threadIdx.x >> 5] = ss;
  __syncthreads();
  if (threadIdx.x == 0) {
    float t = 0.f;
#pragma unroll
    for (int i = 0; i < 8; i++) t += sred[i];
    sscale = rsqrtf(t / (float)cols + 1e-6f);
  }
  __syncthreads();
  float sc = sscale;
  float* yr = y + (size_t)row * cols;
  for (int i = threadIdx.x; i < cols; i += blockDim.x) yr[i] = xr[i] * sc * w[i];
}

// ---------------- tensor-core tf32 GEMM ----------------
// CTA tile 128x128, BK=32, 256 threads (8 warps as 2m x 4n), warp tile 64x32.
// MODE 0: C = A@B
// MODE 1: C = A@B + D
// MODE 2: A rows gathered via g_tok[e]; C[slot] = A@B        (MoE pass 1a: raw g)
// MODE 3: A rows gathered; C[slot] = silu(D[slot]) * (A@B)   (MoE pass 1b)
// MODE 4: A rows = slots (g_off[e]+m); atomicAdd C[token] += w * (A@B)  (MoE pass 2)
template <int MODE>
__global__ void __launch_bounds__(256, 1)
gemm_tc(const float* __restrict__ A, const float* __restrict__ B,
        const float* __restrict__ D, float* __restrict__ C, int N, int K) {
  __shared__ uint32_t As[128 * 36];   // As[m][k], stride 36 words (conflict-free frags)
  __shared__ uint32_t Bs[32 * 136];   // Bs[k][n], stride 136 words
  __shared__ int toks[128];

  const int tid = threadIdx.x;
  const int lane = tid & 31, wid = tid >> 5;
  const int wm = (wid >> 2) * 64, wn = (wid & 3) * 32;
  const int m0 = blockIdx.x * 128, n0 = blockIdx.y * 128;

  int e = 0, ne = 0, off = 0;
  if (MODE >= 2) {
    e = blockIdx.z;
    ne = g_cnt[e];
    off = g_off[e];
    if (m0 >= ne) return;
    B += (size_t)e * (size_t)K * (size_t)N;   // per-expert weight slab
    if (MODE == 2 || MODE == 3) {
      if (tid < 128) {
        int mm = m0 + tid;
        toks[tid] = g_tok[e * SEQ + (mm < ne ? mm : ne - 1)];
      }
      __syncthreads();
    }
  }

  // global pointers for the 4 A-chunks / 4 B-chunks this thread loads per K-slab
  const float* Arow[4];
  const float* Brow[4];
#pragma unroll
  for (int i = 0; i < 4; i++) {
    int idx = tid + i * 256;
    int r = idx >> 3;                  // 0..127
    int row;
    if (MODE == 2 || MODE == 3) row = toks[r];
    else if (MODE == 4) { int mm = m0 + r; if (mm >= ne) mm = ne - 1; row = off + mm; }
    else row = m0 + r;
    Arow[i] = A + (size_t)row * K + ((idx & 7) << 2);
    Brow[i] = B + (size_t)(idx >> 5) * N + n0 + ((idx & 31) << 2);
  }

  float acc[4][4][4];
#pragma unroll
  for (int a = 0; a < 4; a++)
#pragma unroll
    for (int b = 0; b < 4; b++)
#pragma unroll
      for (int c = 0; c < 4; c++) acc[a][b][c] = 0.f;

  float4 pa[4], pb[4];
#pragma unroll
  for (int i = 0; i < 4; i++) { pa[i] = *(const float4*)Arow[i]; pb[i] = *(const float4*)Brow[i]; }

  for (int k0 = 0; k0 < K; k0 += 32) {
    // store prefetched slab to smem (tf32-converted)
#pragma unroll
    for (int i = 0; i < 4; i++) {
      int idx = tid + i * 256;
      uint4 t;
      t.x = f2tf(pa[i].x); t.y = f2tf(pa[i].y); t.z = f2tf(pa[i].z); t.w = f2tf(pa[i].w);
      *(uint4*)&As[(idx >> 3) * 36 + ((idx & 7) << 2)] = t;
      uint4 u;
      u.x = f2tf(pb[i].x); u.y = f2tf(pb[i].y); u.z = f2tf(pb[i].z); u.w = f2tf(pb[i].w);
      *(uint4*)&Bs[(idx >> 5) * 136 + ((idx & 31) << 2)] = u;
    }
    __syncthreads();

    if (k0 + 32 < K) {
#pragma unroll
      for (int i = 0; i < 4; i++) {
        pa[i] = *(const float4*)(Arow[i] + (k0 + 32));
        pb[i] = *(const float4*)(Brow[i] + (size_t)(k0 + 32) * N);
      }
    }

#pragma unroll
    for (int ks = 0; ks < 4; ks++) {
      const int kb = ks * 8;
      uint32_t af[4][4], bf[4][2];
#pragma unroll
      for (int mt = 0; mt < 4; mt++) {
        int rb = wm + mt * 16 + (lane >> 2);
        int cc = kb + (lane & 3);
        af[mt][0] = As[rb * 36 + cc];
        af[mt][1] = As[(rb + 8) * 36 + cc];
        af[mt][2] = As[rb * 36 + cc + 4];
        af[mt][3] = As[(rb + 8) * 36 + cc + 4];
      }
#pragma unroll
      for (int nt = 0; nt < 4; nt++) {
        int cb = wn + nt * 8 + (lane >> 2);
        int rr = kb + (lane & 3);
        bf[nt][0] = Bs[rr * 136 + cb];
        bf[nt][1] = Bs[(rr + 4) * 136 + cb];
      }
#pragma unroll
      for (int mt = 0; mt < 4; mt++)
#pragma unroll
        for (int nt = 0; nt < 4; nt++) mma_tf32(acc[mt][nt], af[mt], bf[nt]);
    }
    __syncthreads();
  }

  // epilogue
#pragma unroll
  for (int mt = 0; mt < 4; mt++) {
#pragma unroll
    for (int half = 0; half < 2; half++) {
      int ml = wm + mt * 16 + (lane >> 2) + half * 8;
      if (MODE == 0 || MODE == 1) {
        size_t rowb = (size_t)(m0 + ml) * N;
#pragma unroll
        for (int nt = 0; nt < 4; nt++) {
          int nn = n0 + wn + nt * 8 + 2 * (lane & 3);
          float v0 = acc[mt][nt][half * 2], v1 = acc[mt][nt][half * 2 + 1];
          if (MODE == 1) { v0 += D[rowb + nn]; v1 += D[rowb + nn + 1]; }
          C[rowb + nn] = v0;
          C[rowb + nn + 1] = v1;
        }
      } else {
        int mm = m0 + ml;
        if (mm < ne) {
          if (MODE == 2) {
            size_t rowb = (size_t)(off + mm) * N;
#pragma unroll
            for (int nt = 0; nt < 4; nt++) {
              int nn = n0 + wn + nt * 8 + 2 * (lane & 3);
              C[rowb + nn] = acc[mt][nt][half * 2];
              C[rowb + nn + 1] = acc[mt][nt][half * 2 + 1];
            }
          } else if (MODE == 3) {
            size_t rowb = (size_t)(off + mm) * N;
#pragma unroll
            for (int nt = 0; nt < 4; nt++) {
              int nn = n0 + wn + nt * 8 + 2 * (lane & 3);
              float g0 = D[rowb + nn], g1 = D[rowb + nn + 1];
              float u0 = acc[mt][nt][half * 2], u1 = acc[mt][nt][half * 2 + 1];
              C[rowb + nn]     = g0 * u0 / (1.f + __expf(-g0));
              C[rowb + nn + 1] = g1 * u1 / (1.f + __expf(-g1));
            }
          } else {  // MODE 4
            int t = g_tok[e * SEQ + mm];
            float w = g_tw[e * SEQ + mm];
            size_t rowb = (size_t)t * HID;
#pragma unroll
            for (int nt = 0; nt < 4; nt++) {
              int nn = n0 + wn + nt * 8 + 2 * (lane & 3);
              atomicAdd(&C[rowb + nn], w * acc[mt][nt][half * 2]);
              atomicAdd(&C[rowb + nn + 1], w * acc[mt][nt][half * 2 + 1]);
            }
          }
        }
      }
    }
  }
}

// ---------------- partial RoPE (first RD=64 dims of each head), in place ----------------
__global__ void rope_kernel(float* __restrict__ x, const float* __restrict__ cp,
                            const float* __restrict__ sp, int nheads) {
  int idx = blockIdx.x * blockDim.x + threadIdx.x;
  int total = SEQ * nheads * 32;
  if (idx >= total) return;
  int d = idx & 31;
  int h = (idx >> 5) % nheads;
  int s = idx / (nheads * 32);
  size_t base = (size_t)s * nheads * HDIM + (size_t)h * HDIM + d;
  float a = x[base], b = x[base + 32];
  float c = cp[s * 64 + d], sn = sp[s * 64 + d];
  x[base]      = a * c - b * sn;
  x[base + 32] = b * c + a * sn;
}

// ---------------- causal flash attention, fp32, Br=Bc=64 ----------------
__global__ void flash_kernel(const float* __restrict__ Q, const float* __restrict__ Kp,
                             const float* __restrict__ Vp, float* __restrict__ O) {
  extern __shared__ float sm[];
  float* Qs = sm;                 // 64 x 132 (padded)
  float* Ks = Qs + 64 * 132;      // 64 x 132
  float* Vs = Ks + 64 * 132;      // 64 x 128
  float* Ps = Vs + 64 * 128;      // 64 x 64
  int qt = blockIdx.x, head = blockIdx.y;
  int kh = head >> 2;             // GQA: 4 query heads per KV head
  int tid = threadIdx.x, tx = tid & 15, ty = tid >> 4;
  int q0 = qt * 64;

  for (int i = tid; i < 64 * 32; i += 256) {
    int r = i >> 5, d4 = (i & 31) << 2;
    *(float4*)&Qs[r * 132 + d4] =
        *(const float4*)&Q[(size_t)(q0 + r) * (NHEADS * HDIM) + head * HDIM + d4];
  }

  float m[4], l[4], co[4][8];
#pragma unroll
  for (int i = 0; i < 4; i++) {
    m[i] = -3.0e38f; l[i] = 0.f;
#pragma unroll
    for (int c = 0; c < 8; c++) co[i][c] = 0.f;
  }

  for (int kt = 0; kt <= qt; kt++) {
    __syncthreads();
    int k0 = kt * 64;
    for (int i = tid; i < 64 * 32; i += 256) {
      int r = i >> 5, d4 = (i & 31) << 2;
      size_t gb = (size_t)(k0 + r) * (NKVH * HDIM) + kh * HDIM + d4;
      *(float4*)&Ks[r * 132 + d4] = *(const float4*)&Kp[gb];
      *(float4*)&Vs[r * 128 + d4] = *(const float4*)&Vp[gb];
    }
    __syncthreads();

    float sc[4][4] = {};
    for (int d = 0; d < 128; d += 4) {
      float4 aa[4], bb[4];
#pragma unroll
      for (int i = 0; i < 4; i++) aa[i] = *(const float4*)&Qs[((ty << 2) + i) * 132 + d];
#pragma unroll
      for (int j = 0; j < 4; j++) bb[j] = *(const float4*)&Ks[((tx << 2) + j) * 132 + d];
#pragma unroll
      for (int i = 0; i < 4; i++)
#pragma unroll
        for (int j = 0; j < 4; j++)
          sc[i][j] += aa[i].x * bb[j].x + aa[i].y * bb[j].y +
                      aa[i].z * bb[j].z + aa[i].w * bb[j].w;
    }

    bool diag = (kt == qt);
#pragma unroll
    for (int i = 0; i < 4; i++) {
      int r = (ty << 2) + i;
#pragma unroll
      for (int j = 0; j < 4; j++) {
        float v = sc[i][j] * ATT_SCALE;
        if (diag && ((tx << 2) + j) > r) v = -1e30f;
        sc[i][j] = v;
      }
      float mx = fmaxf(fmaxf(sc[i][0], sc[i][1]), fmaxf(sc[i][2], sc[i][3]));
#pragma unroll
      for (int o = 8; o; o >>= 1) mx = fmaxf(mx, __shfl_xor_sync(0xffffffffu, mx, o));
      float mn = fmaxf(m[i], mx);
      float corr = __expf(m[i] - mn);
      m[i] = mn;
      float rs = 0.f;
#pragma unroll
      for (int j = 0; j < 4; j++) {
        float p = __expf(sc[i][j] - mn);
        sc[i][j] = p; rs += p;
      }
#pragma unroll
      for (int o = 8; o; o >>= 1) rs += __shfl_xor_sync(0xffffffffu, rs, o);
      l[i] = l[i] * corr + rs;
#pragma unroll
      for (int c = 0; c < 8; c++) co[i][c] *= corr;
#pragma unroll
      for (int j = 0; j < 4; j++) Ps[r * 64 + (tx << 2) + j] = sc[i][j];
    }
    __syncthreads();

    for (int j = 0; j < 64; j++) {
      float4 v0 = *(const float4*)&Vs[j * 128 + (tx << 3)];
      float4 v1 = *(const float4*)&Vs[j * 128 + (tx << 3) + 4];
#pragma unroll
      for (int i = 0; i < 4; i++) {
        float p = Ps[((ty << 2) + i) * 64 + j];
        co[i][0] += p * v0.x; co[i][1] += p * v0.y;
        co[i][2] += p * v0.z; co[i][3] += p * v0.w;
        co[i][4] += p * v1.x; co[i][5] += p * v1.y;
        co[i][6] += p * v1.z; co[i][7] += p * v1.w;
      }
    }
  }

#pragma unroll
  for (int i = 0; i < 4; i++) {
    float inv = 1.f / l[i];
    int r = q0 + (ty << 2) + i;
#pragma unroll
    for (int c = 0; c < 8; c++)
      O[(size_t)r * (NHEADS * HDIM) + head * HDIM + (tx << 3) + c] = co[i][c] * inv;
  }
}

// ---------------- MoE gating: sigmoid, top-2, normalized weights (fp32) ----------------
__global__ void gate_kernel(const float* __restrict__ X, const float* __restrict__ GW,
                            const float* __restrict__ BE) {
  int t = blockIdx.x;
  const float* xr = X + (size_t)t * HID;
  float acc[NEXP];
#pragma unroll
  for (int e = 0; e < NEXP; e++) acc[e] = 0.f;
  for (int h = threadIdx.x; h < HID; h += blockDim.x) {
    float xv = xr[h];
    const float* g = GW + (size_t)h * NEXP;
#pragma unroll
    for (int e = 0; e < NEXP; e++) acc[e] += xv * g[e];
  }
#pragma unroll
  for (int e = 0; e < NEXP; e++)
#pragma unroll
    for (int o = 16; o; o >>= 1) acc[e] += __shfl_xor_sync(0xffffffffu, acc[e], o);
  __shared__ float ws[8][NEXP];
  if ((threadIdx.x & 31) == 0)
#pragma unroll
    for (int e = 0; e < NEXP; e++) ws[threadIdx.x >> 5][e] = acc[e];
  __syncthreads();
  if (threadIdx.x == 0) {
    float scv[NEXP], bi[NEXP];
#pragma unroll
    for (int e = 0; e < NEXP; e++) {
      float lg = 0.f;
#pragma unroll
      for (int wdx = 0; wdx < 8; wdx++) lg += ws[wdx][e];
      scv[e] = 1.f / (1.f + expf(-lg));
      bi[e] = scv[e] + BE[e];
    }
    int i0 = 0;
    for (int e = 1; e < NEXP; e++) if (bi[e] > bi[i0]) i0 = e;
    int i1 = -1;
    for (int e = 0; e < NEXP; e++) {
      if (e == i0) continue;
      if (i1 < 0 || bi[e] > bi[i1]) i1 = e;
    }
    float w0 = scv[i0], w1 = scv[i1];
    float ssum = fmaxf(w0 + w1, 1e-12f);
    g_topidx[t * 2] = i0; g_topidx[t * 2 + 1] = i1;
    g_topw[t * 2] = w0 / ssum; g_topw[t * 2 + 1] = w1 / ssum;
  }
}

__global__ void zero_cnt_kernel() {
  if (threadIdx.x < NEXP) g_cnt[threadIdx.x] = 0;
}

__global__ void route_kernel() {
  int s = blockIdx.x * blockDim.x + threadIdx.x;
  if (s >= SEQ * 2) return;
  int e = g_topidx[s];
  float w = g_topw[s];
  int p = atomicAdd(&g_cnt[e], 1);
  g_tok[e * SEQ + p] = s >> 1;
  g_tw[e * SEQ + p] = w;
}

__global__ void offsets_kernel() {
  if (threadIdx.x == 0) {
    int s = 0;
    for (int e = 0; e < NEXP; e++) { g_off[e] = s; s += g_cnt[e]; }
  }
}

// ---------------- launch ----------------
extern "C" void kernel_launch(void* const* d_in, const int* in_sizes, int n_in,
                              void* d_out, int out_size) {
  const float* hidden = (const float*)d_in[0];
  // d_in[1] = attention_mask: exact causal triu(-1e9) — implemented as causal attention
  const float* cosp = (const float*)d_in[2];
  const float* sinp = (const float*)d_in[3];
  const float* ln1  = (const float*)d_in[4];
  const float* ln2  = (const float*)d_in[5];
  const float* wq   = (const float*)d_in[6];
  const float* wk   = (const float*)d_in[7];
  const float* wv   = (const float*)d_in[8];
  const float* wo   = (const float*)d_in[9];
  const float* qn   = (const float*)d_in[10];
  const float* kn   = (const float*)d_in[11];
  const float* gw   = (const float*)d_in[12];
  const float* be   = (const float*)d_in[13];
  const float* w1   = (const float*)d_in[14];
  const float* w3   = (const float*)d_in[15];
  const float* w2   = (const float*)d_in[16];
  float* out = (float*)d_out;

  float *x1, *q, *k, *v, *attn, *x3, *moeh, *tmp;
  cudaGetSymbolAddress((void**)&x1, g_x1);
  cudaGetSymbolAddress((void**)&q, g_q);
  cudaGetSymbolAddress((void**)&k, g_k);
  cudaGetSymbolAddress((void**)&v, g_v);
  cudaGetSymbolAddress((void**)&attn, g_attn);
  cudaGetSymbolAddress((void**)&x3, g_x3);
  cudaGetSymbolAddress((void**)&moeh, g_moeh);
  cudaGetSymbolAddress((void**)&tmp, g_tmp);

  // 1) ln1
  rmsnorm_kernel<<<SEQ, 256>>>(hidden, ln1, x1, HID);
  // 2) QKV projections (tf32 tensor cores)
  gemm_tc<0><<<dim3(16, 16), 256>>>(x1, wq, nullptr, q, 2048, 2048);
  gemm_tc<0><<<dim3(16, 4), 256>>>(x1, wk, nullptr, k, 512, 2048);
  gemm_tc<0><<<dim3(16, 4), 256>>>(x1, wv, nullptr, v, 512, 2048);
  // 3) q/k norm (full-width, in place) + partial RoPE
  rmsnorm_kernel<<<SEQ, 256>>>(q, qn, q, 2048);
  rmsnorm_kernel<<<SEQ, 256>>>(k, kn, k, 512);
  rope_kernel<<<(SEQ * NHEADS * 32) / 256, 256>>>(q, cosp, sinp, NHEADS);
  rope_kernel<<<(SEQ * NKVH * 32) / 256, 256>>>(k, cosp, sinp, NKVH);
  // 4) causal flash attention (fp32)
  int fasmem = (64 * 132 * 2 + 64 * 128 + 64 * 64) * (int)sizeof(float);  // 116736 B
  cudaFuncSetAttribute(flash_kernel, cudaFuncAttributeMaxDynamicSharedMemorySize, fasmem);
  flash_kernel<<<dim3(32, NHEADS), 256, fasmem>>>(q, k, v, attn);
  // 5) wo + residual -> d_out (acts as res2)
  gemm_tc<1><<<dim3(16, 16), 256>>>(attn, wo, hidden, out, 2048, 2048);
  // 6) ln2
  rmsnorm_kernel<<<SEQ, 256>>>(out, ln2, x3, HID);
  // 7) gating + routing (fp32 — keeps top-k selection exact)
  gate_kernel<<<SEQ, 256>>>(x3, gw, be);
  zero_cnt_kernel<<<1, 32>>>();
  route_kernel<<<16, 256>>>();
  offsets_kernel<<<1, 32>>>();
  // 8) sparse MoE (tf32 tensor cores)
  gemm_tc<2><<<dim3(16, 8, 8), 256>>>(x3, w1, nullptr, tmp, IDIM, HID);   // raw g
  gemm_tc<3><<<dim3(16, 8, 8), 256>>>(x3, w3, tmp, moeh, IDIM, HID);      // silu(g)*u
  gemm_tc<4><<<dim3(16, 16, 8), 256>>>(moeh, w2, nullptr, out, HID, IDIM); // scatter-add
}